// round 4
// baseline (speedup 1.0000x reference)
#include <cuda_runtime.h>

#define NCH    129
#define T      64000
#define BS     8
#define LFRM   256
#define NFRM   250
#define NCHUNK 125
#define CHUNK  512       // exactly 2 frames per chunk (2*NCHUNK == NFRM)
#define WARM   384       // fast states only: 0.97^384=e^-11.7, beta^384~e^-48

#define ALPHA  0.992217938260243520f   // exp(-1/128)
#define BETA   0.882496902584595400f   // exp(-1/8)
#define NL2E  -1.4426950408889634f     // -log2(e), folded into B coeffs

// alpha powers for the chunk-scan correction
#define A_POW_CHUNK 0.0183156388887342f   // exp(-512/128) = e^-4
#define A_POW_1     0.9922179382602435f   // alpha^1
#define A_POW_257   0.1342820882f          // alpha^257 = exp(-257/128)

typedef unsigned long long u64;

// Scratch: batch-paired waveform, (BS/2) x T float2 = 2 MB
__device__ float2 g_pair[(BS / 2) * T];
// Per-chunk alpha-IIR tail sums: S[c][b][ch]
__device__ float g_S[NCHUNK * BS * NCH];

__global__ void pair_kernel(const float* __restrict__ wav)
{
    int i = blockIdx.x * blockDim.x + threadIdx.x;
    if (i >= (BS / 2) * T) return;
    int p = i / T, t = i % T;
    g_pair[i] = make_float2(wav[(2 * p) * T + t], wav[(2 * p + 1) * T + t]);
}

__device__ __forceinline__ u64 pack2(float lo, float hi) {
    u64 r; asm("mov.b64 %0, {%1, %2};" : "=l"(r) : "f"(lo), "f"(hi)); return r;
}
__device__ __forceinline__ void unpack2(u64 v, float& lo, float& hi) {
    asm("mov.b64 {%0, %1}, %2;" : "=f"(lo), "=f"(hi) : "l"(v));
}
#define FMA2(d,a,b,c) asm("fma.rn.f32x2 %0, %1, %2, %3;" : "=l"(d) : "l"(a), "l"(b), "l"(c))
#define MUL2(d,a,b)   asm("mul.rn.f32x2 %0, %1, %2;"     : "=l"(d) : "l"(a), "l"(b))
__device__ __forceinline__ float ex2a(float x) {
    float r; asm("ex2.approx.f32 %0, %1;" : "=f"(r) : "f"(x)); return r;
}
__device__ __forceinline__ float rcpa(float x) {
    float r; asm("rcp.approx.f32 %0, %1;" : "=f"(r) : "f"(x)); return r;
}

__global__ __launch_bounds__(32)
void aud_spec_kernel(const float* __restrict__ cB,
                     const float* __restrict__ cA,
                     float* __restrict__ out)
{
    // One warp per (channel-group w, batch-pair p, time-chunk c).
    const int warpId = blockIdx.x;
    const int w    = warpId % 5;
    const int rem  = warpId / 5;
    const int p    = rem % (BS / 2);
    const int c    = rem / (BS / 2);
    const int lane = threadIdx.x;

    const int chRaw = 31 * w + lane;
    const int ch    = (chRaw > NCH - 1) ? (NCH - 1) : chRaw;

    const float* Bc = cB + ch * 5;
    const float* Ac = cA + ch * 5;
    const float b0 = NL2E * Bc[0], b1 = NL2E * Bc[1], b2 = NL2E * Bc[2],
                b3 = NL2E * Bc[3], b4 = NL2E * Bc[4];
    const u64 B0p = pack2(b0, b0), B1p = pack2(b1, b1), B2p = pack2(b2, b2),
              B3p = pack2(b3, b3), B4p = pack2(b4, b4);
    const u64 A1p = pack2(-Ac[1], -Ac[1]);
    const u64 A2p = pack2(-Ac[2], -Ac[2]);
    const u64 A3p = pack2(-Ac[3], -Ac[3]);
    const u64 A4p = pack2(-Ac[4], -Ac[4]);

    u64 z0 = 0, z1 = 0, z2 = 0, z3 = 0;     // packed IIR state (TDF-II)
    float v0 = 0.f, v1 = 0.f;                // beta IIR
    float u0 = 0.f, u1 = 0.f;                // alpha IIR, ZERO-INIT per chunk

    const u64* x = reinterpret_cast<const u64*>(g_pair + p * T);
    const int cstart = c * CHUNK;
    int ws = cstart - WARM;
    if (ws < 0) ws = 0;

    const bool doStore = (chRaw <= NCH - 1) && (lane > 0 || w == 0);
    float* outA = out + ((2 * p)     * NCH + ch) * NFRM;
    float* outB = out + ((2 * p + 1) * NCH + ch) * NFRM;

#define STEP(xx) {                                                     \
    u64 y_, t_;                                                        \
    FMA2(y_, B0p, (xx), z0);                                           \
    FMA2(t_, B1p, (xx), z1); FMA2(z0, A1p, y_, t_);                    \
    FMA2(t_, B2p, (xx), z2); FMA2(z1, A2p, y_, t_);                    \
    FMA2(t_, B3p, (xx), z3); FMA2(z2, A3p, y_, t_);                    \
    MUL2(t_, B4p, (xx));     FMA2(z3, A4p, y_, t_);                    \
    float y0_, y1_; unpack2(y_, y0_, y1_);                             \
    float s0_ = rcpa(1.0f + ex2a(y0_));                                \
    float s1_ = rcpa(1.0f + ex2a(y1_));                                \
    v0 = fmaf(BETA, v0, s0_);                                          \
    v1 = fmaf(BETA, v1, s1_);                                          \
    float vp0_ = __shfl_up_sync(0xffffffffu, v0, 1);                   \
    float vp1_ = __shfl_up_sync(0xffffffffu, v1, 1);                   \
    u0 = fmaf(ALPHA, u0, fmaxf(v0 - vp0_, 0.0f));                      \
    u1 = fmaf(ALPHA, u1, fmaxf(v1 - vp1_, 0.0f));                      \
}

    // Warm-up: settles z (pole r<=0.97) and v (beta); u's long-memory part
    // is reconstructed exactly by the fixup scan, so no alpha warm needed.
    // (u accumulates garbage here; reset below.)
    for (int t = ws; t < cstart; t += 4) {
        const ulonglong2 q0 = *reinterpret_cast<const ulonglong2*>(x + t);
        const ulonglong2 q1 = *reinterpret_cast<const ulonglong2*>(x + t + 2);
        STEP(q0.x); STEP(q0.y); STEP(q1.x); STEP(q1.y);
    }
    u0 = 0.f; u1 = 0.f;   // zero-init local alpha-IIR at chunk start

    // Main: frames at t % 256 == 0; store the LOCAL u (corrected later).
    const int cend = cstart + CHUNK;
    for (int t = cstart; t < cend; t += 4) {
        const ulonglong2 q0 = *reinterpret_cast<const ulonglong2*>(x + t);
        const ulonglong2 q1 = *reinterpret_cast<const ulonglong2*>(x + t + 2);
        STEP(q0.x);
        if ((t & (LFRM - 1)) == 0) {
            if (doStore) { outA[t >> 8] = u0; outB[t >> 8] = u1; }
        }
        STEP(q0.y); STEP(q1.x); STEP(q1.y);
    }
#undef STEP

    // Chunk tail sum S_c = zero-init u at end of chunk (exact scan term).
    if (doStore) {
        g_S[(c * BS + 2 * p)     * NCH + ch] = u0;
        g_S[(c * BS + 2 * p + 1) * NCH + ch] = u1;
    }
}

// Exact cross-chunk correction: U(c) = a^CHUNK * U(c-1) + S_c;
// frame at offset 0 gets += a^1 * U(c-1), offset 256 gets += a^257 * U(c-1).
__global__ void fixup_kernel(float* __restrict__ out)
{
    int tid = blockIdx.x * blockDim.x + threadIdx.x;   // over BS*NCH
    if (tid >= BS * NCH) return;
    const int b  = tid / NCH;
    const int ch = tid % NCH;
    float* o = out + (b * NCH + ch) * NFRM;

    float U = 0.f;   // true u state entering chunk c
    #pragma unroll 1
    for (int c = 0; c < NCHUNK; c++) {
        o[2 * c]     += A_POW_1   * U;
        o[2 * c + 1] += A_POW_257 * U;
        U = fmaf(A_POW_CHUNK, U, g_S[(c * BS + b) * NCH + ch]);
    }
}

extern "C" void kernel_launch(void* const* d_in, const int* in_sizes, int n_in,
                              void* d_out, int out_size)
{
    const float* wav = (const float*)d_in[0];   // (BS, T)
    const float* cB  = (const float*)d_in[1];   // (NCH, 5)
    const float* cA  = (const float*)d_in[2];   // (NCH, 5)
    float* out = (float*)d_out;                 // (BS, NCH, NFRM)

    const int nPair = (BS / 2) * T;
    pair_kernel<<<(nPair + 255) / 256, 256>>>(wav);

    const int nWarps = 5 * (BS / 2) * NCHUNK;   // 2500
    aud_spec_kernel<<<nWarps, 32>>>(cB, cA, out);

    fixup_kernel<<<(BS * NCH + 127) / 128, 128>>>(out);
}

// round 5
// speedup vs baseline: 1.4823x; 1.4823x over previous
#include <cuda_runtime.h>

#define NCH    129
#define T      64000
#define BS     8
#define NFRM   250
#define NCHUNK 125
#define CHUNK  512       // 2 frames per chunk
#define WARM   384       // fast states: 0.97^384=e^-11.7, beta^384~e^-48

#define ALPHA  0.992217938260243520f   // exp(-1/128)
#define BETA   0.882496902584595400f   // exp(-1/8)

// alpha powers for the cross-chunk scan correction
#define A_POW_CHUNK 0.0183156388887342f   // alpha^512 = e^-4
#define A_POW_1     0.9922179382602435f   // alpha^1
#define A_POW_257   0.1342820882f         // alpha^257

typedef unsigned long long u64;

// Per-chunk local-alpha-IIR tail sums: S[c][b][ch]  (coalesced for fixup)
__device__ float g_S[NCHUNK * BS * NCH];

__device__ __forceinline__ u64 pack2(float lo, float hi) {
    u64 r; asm("mov.b64 %0, {%1, %2};" : "=l"(r) : "f"(lo), "f"(hi)); return r;
}
__device__ __forceinline__ void unpack2(u64 v, float& lo, float& hi) {
    asm("mov.b64 {%0, %1}, %2;" : "=f"(lo), "=f"(hi) : "l"(v));
}
#define FMA2(d,a,b,c) asm("fma.rn.f32x2 %0, %1, %2, %3;" : "=l"(d) : "l"(a), "l"(b), "l"(c))
#define MUL2(d,a,b)   asm("mul.rn.f32x2 %0, %1, %2;"     : "=l"(d) : "l"(a), "l"(b))
__device__ __forceinline__ float tanha(float x) {
    float r; asm("tanh.approx.f32 %0, %1;" : "=f"(r) : "f"(x)); return r;
}

__global__ __launch_bounds__(128)
void aud_spec_kernel(const float* __restrict__ wav,
                     const float* __restrict__ cB,
                     const float* __restrict__ cA,
                     float* __restrict__ out)
{
    // One warp per (channel-group w, batch-pair p, time-chunk c).
    const int warpId = blockIdx.x * 4 + (threadIdx.x >> 5);
    const int w    = warpId % 5;
    const int rem  = warpId / 5;
    const int p    = rem % (BS / 2);
    const int c    = rem / (BS / 2);
    const int lane = threadIdx.x & 31;

    const int chRaw = 31 * w + lane;
    const int ch    = (chRaw > NCH - 1) ? (NCH - 1) : chRaw;

    const float* Bc = cB + ch * 5;
    const float* Ac = cA + ch * 5;
    // Fold the sigmoid's 1/2 argument scale into B: y_ = 0.5*y1.
    const float b0 = 0.5f * Bc[0], b1 = 0.5f * Bc[1], b2 = 0.5f * Bc[2],
                b3 = 0.5f * Bc[3], b4 = 0.5f * Bc[4];
    const u64 B0p = pack2(b0, b0), B1p = pack2(b1, b1), B2p = pack2(b2, b2),
              B3p = pack2(b3, b3), B4p = pack2(b4, b4);
    const u64 A1p = pack2(-Ac[1], -Ac[1]);
    const u64 A2p = pack2(-Ac[2], -Ac[2]);
    const u64 A3p = pack2(-Ac[3], -Ac[3]);
    const u64 A4p = pack2(-Ac[4], -Ac[4]);

    u64 z0 = 0, z1 = 0, z2 = 0, z3 = 0;   // packed IIR state (TDF-II)
    float v0 = 0.f, v1 = 0.f;              // beta IIR
    float u0 = 0.f, u1 = 0.f;              // alpha IIR (local, zero-init)

    const float4* xa4 = reinterpret_cast<const float4*>(wav + (2 * p)     * T);
    const float4* xb4 = reinterpret_cast<const float4*>(wav + (2 * p + 1) * T);

    const int cstart = c * CHUNK;
    int ws = cstart - WARM;
    if (ws < 0) ws = 0;

    const bool doStore = (chRaw <= NCH - 1) && (lane > 0 || w == 0);
    float* outA = out + ((2 * p)     * NCH + ch) * NFRM;
    float* outB = out + ((2 * p + 1) * NCH + ch) * NFRM;

#define STEP(xx) {                                                     \
    u64 y_, t_;                                                        \
    FMA2(y_, B0p, (xx), z0);                                           \
    FMA2(t_, B1p, (xx), z1); FMA2(z0, A1p, y_, t_);                    \
    FMA2(t_, B2p, (xx), z2); FMA2(z1, A2p, y_, t_);                    \
    FMA2(t_, B3p, (xx), z3); FMA2(z2, A3p, y_, t_);                    \
    MUL2(t_, B4p, (xx));     FMA2(z3, A4p, y_, t_);                    \
    float y0_, y1_; unpack2(y_, y0_, y1_);                             \
    float th0_ = tanha(y0_);                                           \
    float th1_ = tanha(y1_);                                           \
    v0 = fmaf(BETA, v0, fmaf(0.5f, th0_, 0.5f));                       \
    v1 = fmaf(BETA, v1, fmaf(0.5f, th1_, 0.5f));                       \
    float vp0_ = __shfl_up_sync(0xffffffffu, v0, 1);                   \
    float vp1_ = __shfl_up_sync(0xffffffffu, v1, 1);                   \
    u0 = fmaf(ALPHA, u0, fmaxf(v0 - vp0_, 0.0f));                      \
    u1 = fmaf(ALPHA, u1, fmaxf(v1 - vp1_, 0.0f));                      \
}

    int g = ws >> 2;                     // group index (4 samples/group)
    const int gWarmEnd = cstart >> 2;
    const int gEnd = (cstart + CHUNK) >> 2;
    const int gLast = (T >> 2) - 1;

    float4 a = __ldg(xa4 + g);
    float4 b = __ldg(xb4 + g);

    // Warm-up: settles z (poles) and v (beta). u's long memory is
    // reconstructed exactly by the fixup scan.
    for (; g < gWarmEnd; ) {
        const int gn = g + 1;
        const float4 an = __ldg(xa4 + gn);
        const float4 bn = __ldg(xb4 + gn);
        STEP(pack2(a.x, b.x)); STEP(pack2(a.y, b.y));
        STEP(pack2(a.z, b.z)); STEP(pack2(a.w, b.w));
        a = an; b = bn; g = gn;
    }
    u0 = 0.f; u1 = 0.f;                  // zero-init local alpha IIR

    // Main: frames at g % 64 == 0 (t % 256 == 0), frame idx = g>>6.
    for (; g < gEnd; g++) {
        const int gn = (g + 1 > gLast) ? gLast : g + 1;
        const float4 an = __ldg(xa4 + gn);
        const float4 bn = __ldg(xb4 + gn);
        STEP(pack2(a.x, b.x));
        if ((g & 63) == 0) {
            if (doStore) { outA[g >> 6] = u0; outB[g >> 6] = u1; }
        }
        STEP(pack2(a.y, b.y));
        STEP(pack2(a.z, b.z));
        STEP(pack2(a.w, b.w));
        a = an; b = bn;
    }
#undef STEP

    // Chunk tail sum S_c (zero-init u at chunk end) for the exact scan.
    if (doStore) {
        g_S[(c * BS + 2 * p)     * NCH + ch] = u0;
        g_S[(c * BS + 2 * p + 1) * NCH + ch] = u1;
    }
}

// Exact cross-chunk correction: U(c) = a^CHUNK * U(c-1) + S_c;
// frame at chunk-local offset 0 gets += a^1*U, offset 256 gets += a^257*U.
__global__ void fixup_kernel(float* __restrict__ out)
{
    int tid = blockIdx.x * blockDim.x + threadIdx.x;   // over BS*NCH
    if (tid >= BS * NCH) return;
    const int b  = tid / NCH;
    const int ch = tid % NCH;
    float* o = out + (b * NCH + ch) * NFRM;
    const int base = b * NCH + ch;

    float U = 0.f;
    #pragma unroll 1
    for (int c0 = 0; c0 < NCHUNK; c0 += 5) {
        float S[5];
        #pragma unroll
        for (int j = 0; j < 5; j++)
            S[j] = g_S[(c0 + j) * (BS * NCH) + base];
        #pragma unroll
        for (int j = 0; j < 5; j++) {
            const int c = c0 + j;
            o[2 * c]     += A_POW_1   * U;
            o[2 * c + 1] += A_POW_257 * U;
            U = fmaf(A_POW_CHUNK, U, S[j]);
        }
    }
}

extern "C" void kernel_launch(void* const* d_in, const int* in_sizes, int n_in,
                              void* d_out, int out_size)
{
    const float* wav = (const float*)d_in[0];   // (BS, T)
    const float* cB  = (const float*)d_in[1];   // (NCH, 5)
    const float* cA  = (const float*)d_in[2];   // (NCH, 5)
    float* out = (float*)d_out;                 // (BS, NCH, NFRM)

    const int nWarps = 5 * (BS / 2) * NCHUNK;   // 2500
    aud_spec_kernel<<<nWarps / 4, 128>>>(wav, cB, cA, out);

    fixup_kernel<<<(BS * NCH + 127) / 128, 128>>>(out);
}

// round 6
// speedup vs baseline: 1.8262x; 1.2320x over previous
#include <cuda_runtime.h>

#define NCH    129
#define T      64000
#define BS     8
#define NFRM   250
#define NCHUNK 125
#define CHUNK  512       // 2 frames per chunk
#define WARM   384       // fast states: 0.97^384=e^-11.7, beta^384~e^-48

#define ALPHA  0.992217938260243520f   // exp(-1/128)
#define BETA   0.882496902584595400f   // exp(-1/8)

// alpha powers for the truncated cross-chunk correction
#define Q1     0.0183156388887342f     // alpha^512  = e^-4
#define Q2     0.0003354626279025f     // alpha^1024 = e^-8
#define A_POW_1     0.9922179382602435f   // alpha^1
#define A_POW_257   0.1342820882f         // alpha^257

typedef unsigned long long u64;

// Per-chunk local-alpha-IIR tail sums: S[c][b][ch]
__device__ float g_S[NCHUNK * BS * NCH];

__device__ __forceinline__ u64 pack2(float lo, float hi) {
    u64 r; asm("mov.b64 %0, {%1, %2};" : "=l"(r) : "f"(lo), "f"(hi)); return r;
}
__device__ __forceinline__ void unpack2(u64 v, float& lo, float& hi) {
    asm("mov.b64 {%0, %1}, %2;" : "=f"(lo), "=f"(hi) : "l"(v));
}
#define FMA2(d,a,b,c) asm("fma.rn.f32x2 %0, %1, %2, %3;" : "=l"(d) : "l"(a), "l"(b), "l"(c))
#define MUL2(d,a,b)   asm("mul.rn.f32x2 %0, %1, %2;"     : "=l"(d) : "l"(a), "l"(b))
__device__ __forceinline__ float tanha(float x) {
    float r; asm("tanh.approx.f32 %0, %1;" : "=f"(r) : "f"(x)); return r;
}

__global__ __launch_bounds__(128)
void aud_spec_kernel(const float* __restrict__ wav,
                     const float* __restrict__ cB,
                     const float* __restrict__ cA,
                     float* __restrict__ out)
{
    // One warp per (channel-group w, batch-pair p, time-chunk c).
    const int warpId = blockIdx.x * 4 + (threadIdx.x >> 5);
    const int w    = warpId % 5;
    const int rem  = warpId / 5;
    const int p    = rem % (BS / 2);
    const int c    = rem / (BS / 2);
    const int lane = threadIdx.x & 31;

    const int chRaw = 31 * w + lane;
    const int ch    = (chRaw > NCH - 1) ? (NCH - 1) : chRaw;

    const float* Bc = cB + ch * 5;
    const float* Ac = cA + ch * 5;
    // Fold the sigmoid's 1/2 argument scale into B (tanh form).
    const float b0 = 0.5f * Bc[0], b1 = 0.5f * Bc[1], b2 = 0.5f * Bc[2],
                b3 = 0.5f * Bc[3], b4 = 0.5f * Bc[4];
    const u64 B0p = pack2(b0, b0), B1p = pack2(b1, b1), B2p = pack2(b2, b2),
              B3p = pack2(b3, b3), B4p = pack2(b4, b4);
    const u64 A1p = pack2(-Ac[1], -Ac[1]);
    const u64 A2p = pack2(-Ac[2], -Ac[2]);
    const u64 A3p = pack2(-Ac[3], -Ac[3]);
    const u64 A4p = pack2(-Ac[4], -Ac[4]);

    u64 z0 = 0, z1 = 0, z2 = 0, z3 = 0;   // packed IIR state (TDF-II)
    // w-recurrence: w = beta*w + tanh(y/2).  (v = 0.5*w + 0.5/(1-beta);
    // the affine part cancels exactly in the cross-channel diff, and the
    // 0.5 scale is applied at store time: u_true = 0.5 * u_local.)
    float w0 = 0.f, w1 = 0.f;
    float u0 = 0.f, u1 = 0.f;              // scaled alpha IIR (local)

    const float4* xa4 = reinterpret_cast<const float4*>(wav + (2 * p)     * T);
    const float4* xb4 = reinterpret_cast<const float4*>(wav + (2 * p + 1) * T);

    const int cstart = c * CHUNK;
    int ws = cstart - WARM;
    if (ws < 0) ws = 0;

    const bool doStore = (chRaw <= NCH - 1) && (lane > 0 || w == 0);
    float* outA = out + ((2 * p)     * NCH + ch) * NFRM;
    float* outB = out + ((2 * p + 1) * NCH + ch) * NFRM;

#define STEP(xx) {                                                     \
    u64 y_, t_;                                                        \
    FMA2(y_, B0p, (xx), z0);                                           \
    FMA2(t_, B1p, (xx), z1); FMA2(z0, A1p, y_, t_);                    \
    FMA2(t_, B2p, (xx), z2); FMA2(z1, A2p, y_, t_);                    \
    FMA2(t_, B3p, (xx), z3); FMA2(z2, A3p, y_, t_);                    \
    MUL2(t_, B4p, (xx));     FMA2(z3, A4p, y_, t_);                    \
    float y0_, y1_; unpack2(y_, y0_, y1_);                             \
    w0 = fmaf(BETA, w0, tanha(y0_));                                   \
    w1 = fmaf(BETA, w1, tanha(y1_));                                   \
    float wp0_ = __shfl_up_sync(0xffffffffu, w0, 1);                   \
    float wp1_ = __shfl_up_sync(0xffffffffu, w1, 1);                   \
    u0 = fmaf(ALPHA, u0, fmaxf(w0 - wp0_, 0.0f));                      \
    u1 = fmaf(ALPHA, u1, fmaxf(w1 - wp1_, 0.0f));                      \
}

    int g = ws >> 2;                     // group index (4 samples/group)
    const int gWarmEnd = cstart >> 2;
    const int gEnd = (cstart + CHUNK) >> 2;
    const int gLast = (T >> 2) - 1;

    float4 a = __ldg(xa4 + g);
    float4 b = __ldg(xb4 + g);

    // Warm-up: settles z (poles) and w (beta); u's long memory comes from
    // the fixup correction.
    for (; g < gWarmEnd; ) {
        const int gn = g + 1;
        const float4 an = __ldg(xa4 + gn);
        const float4 bn = __ldg(xb4 + gn);
        STEP(pack2(a.x, b.x)); STEP(pack2(a.y, b.y));
        STEP(pack2(a.z, b.z)); STEP(pack2(a.w, b.w));
        a = an; b = bn; g = gn;
    }
    u0 = 0.f; u1 = 0.f;                  // zero-init local alpha IIR

    // Main: frames at g % 64 == 0; store 0.5*u (descale).
    for (; g < gEnd; g++) {
        const int gn = (g + 1 > gLast) ? gLast : g + 1;
        const float4 an = __ldg(xa4 + gn);
        const float4 bn = __ldg(xb4 + gn);
        STEP(pack2(a.x, b.x));
        if ((g & 63) == 0) {
            if (doStore) { outA[g >> 6] = 0.5f * u0; outB[g >> 6] = 0.5f * u1; }
        }
        STEP(pack2(a.y, b.y));
        STEP(pack2(a.z, b.z));
        STEP(pack2(a.w, b.w));
        a = an; b = bn;
    }
#undef STEP

    // Chunk tail sum (descaled) for the cross-chunk correction.
    if (doStore) {
        g_S[(c * BS + 2 * p)     * NCH + ch] = 0.5f * u0;
        g_S[(c * BS + 2 * p + 1) * NCH + ch] = 0.5f * u1;
    }
}

// Fully parallel truncated correction:
//   U(c) = S[c-1] + q*S[c-2] + q^2*S[c-3]   (q = alpha^CHUNK = e^-4;
//   dropped tail <= q^3 = e^-12 ~ 6e-6 relative — below error floor)
//   o[2c]   += alpha^1   * U(c)
//   o[2c+1] += alpha^257 * U(c)
__global__ void fixup_kernel(float* __restrict__ out)
{
    int tid = blockIdx.x * blockDim.x + threadIdx.x;   // over NCHUNK*BS*NCH
    if (tid >= NCHUNK * BS * NCH) return;
    const int ch = tid % NCH;
    const int b  = (tid / NCH) % BS;
    const int c  = tid / (BS * NCH);
    if (c == 0) return;                 // U(0) = 0

    const int base = b * NCH + ch;
    float U = g_S[(c - 1) * (BS * NCH) + base];
    if (c >= 2) U = fmaf(Q1, g_S[(c - 2) * (BS * NCH) + base], U);
    if (c >= 3) U = fmaf(Q2, g_S[(c - 3) * (BS * NCH) + base], U);

    float* o = out + base * NFRM;
    o[2 * c]     += A_POW_1   * U;
    o[2 * c + 1] += A_POW_257 * U;
}

extern "C" void kernel_launch(void* const* d_in, const int* in_sizes, int n_in,
                              void* d_out, int out_size)
{
    const float* wav = (const float*)d_in[0];   // (BS, T)
    const float* cB  = (const float*)d_in[1];   // (NCH, 5)
    const float* cA  = (const float*)d_in[2];   // (NCH, 5)
    float* out = (float*)d_out;                 // (BS, NCH, NFRM)

    const int nWarps = 5 * (BS / 2) * NCHUNK;   // 2500
    aud_spec_kernel<<<nWarps / 4, 128>>>(wav, cB, cA, out);

    const int nFix = NCHUNK * BS * NCH;
    fixup_kernel<<<(nFix + 255) / 256, 256>>>(out);
}

// round 7
// speedup vs baseline: 1.9615x; 1.0741x over previous
#include <cuda_runtime.h>

#define NCH    129
#define T      64000
#define BS     8
#define NFRM   250
#define NCHUNK 125
#define CHUNK  512       // 2 frames per chunk
#define WARM   384       // z warm total; 0.97^384 = e^-11.7
#define WARMW  128       // w warm (beta^128 = e^-16)

#define ALPHA  0.992217938260243520f   // exp(-1/128)
#define BETA   0.882496902584595400f   // exp(-1/8)

// alpha powers for the truncated cross-chunk correction
#define Q1     0.0183156388887342f     // alpha^512  = e^-4
#define Q2     0.0003354626279025f     // alpha^1024 = e^-8
#define A_POW_1     0.9922179382602435f   // alpha^1
#define A_POW_257   0.1342820882f         // alpha^257

typedef unsigned long long u64;

// Per-chunk local-alpha-IIR tail sums: S[c][b][ch]
__device__ float g_S[NCHUNK * BS * NCH];

__device__ __forceinline__ u64 pack2(float lo, float hi) {
    u64 r; asm("mov.b64 %0, {%1, %2};" : "=l"(r) : "f"(lo), "f"(hi)); return r;
}
__device__ __forceinline__ void unpack2(u64 v, float& lo, float& hi) {
    asm("mov.b64 {%0, %1}, %2;" : "=f"(lo), "=f"(hi) : "l"(v));
}
#define FMA2(d,a,b,c) asm("fma.rn.f32x2 %0, %1, %2, %3;" : "=l"(d) : "l"(a), "l"(b), "l"(c))
#define MUL2(d,a,b)   asm("mul.rn.f32x2 %0, %1, %2;"     : "=l"(d) : "l"(a), "l"(b))
__device__ __forceinline__ float tanha(float x) {
    float r; asm("tanh.approx.f32 %0, %1;" : "=f"(r) : "f"(x)); return r;
}

__global__ __launch_bounds__(128)
void aud_spec_kernel(const float* __restrict__ wav,
                     const float* __restrict__ cB,
                     const float* __restrict__ cA,
                     float* __restrict__ out)
{
    // One warp per (channel-group w, batch-pair p, time-chunk c).
    const int warpId = blockIdx.x * 4 + (threadIdx.x >> 5);
    const int w    = warpId % 5;
    const int rem  = warpId / 5;
    const int p    = rem % (BS / 2);
    const int c    = rem / (BS / 2);
    const int lane = threadIdx.x & 31;

    const int chRaw = 31 * w + lane;
    const int ch    = (chRaw > NCH - 1) ? (NCH - 1) : chRaw;

    const float* Bc = cB + ch * 5;
    const float* Ac = cA + ch * 5;
    // Fold the sigmoid's 1/2 argument scale into B (tanh form).
    const float b0 = 0.5f * Bc[0], b1 = 0.5f * Bc[1], b2 = 0.5f * Bc[2],
                b3 = 0.5f * Bc[3], b4 = 0.5f * Bc[4];
    const u64 B0p = pack2(b0, b0), B1p = pack2(b1, b1), B2p = pack2(b2, b2),
              B3p = pack2(b3, b3), B4p = pack2(b4, b4);
    const u64 A1p = pack2(-Ac[1], -Ac[1]);
    const u64 A2p = pack2(-Ac[2], -Ac[2]);
    const u64 A3p = pack2(-Ac[3], -Ac[3]);
    const u64 A4p = pack2(-Ac[4], -Ac[4]);

    u64 z0 = 0, z1 = 0, z2 = 0, z3 = 0;   // packed IIR state (TDF-II)
    float w0 = 0.f, w1 = 0.f;              // w = beta*w + tanh(y); affine
                                           // sigmoid part cancels in diff
    float u0 = 0.f, u1 = 0.f;              // scaled alpha IIR (local)

    const float4* xa4 = reinterpret_cast<const float4*>(wav + (2 * p)     * T);
    const float4* xb4 = reinterpret_cast<const float4*>(wav + (2 * p + 1) * T);

    const int cstart = c * CHUNK;
    int ws = cstart - WARM;
    if (ws < 0) ws = 0;
    int wsw = cstart - WARMW;
    if (wsw < 0) wsw = 0;

    const bool doStore = (chRaw <= NCH - 1) && (lane > 0 || w == 0);
    float* outA = out + ((2 * p)     * NCH + ch) * NFRM;
    float* outB = out + ((2 * p + 1) * NCH + ch) * NFRM;

// IIR core (shared by all phases)
#define IIR(xx, y_) {                                                  \
    u64 t_;                                                            \
    FMA2(y_, B0p, (xx), z0);                                           \
    FMA2(t_, B1p, (xx), z1); FMA2(z0, A1p, y_, t_);                    \
    FMA2(t_, B2p, (xx), z2); FMA2(z1, A2p, y_, t_);                    \
    FMA2(t_, B3p, (xx), z3); FMA2(z2, A3p, y_, t_);                    \
    MUL2(t_, B4p, (xx));     FMA2(z3, A4p, y_, t_);                    \
}
// Phase A: z only
#define STEP_Z(xx) { u64 y_; IIR(xx, y_); (void)y_; }
// Phase B: z + w
#define STEP_ZW(xx) {                                                  \
    u64 y_; IIR(xx, y_);                                               \
    float y0_, y1_; unpack2(y_, y0_, y1_);                             \
    w0 = fmaf(BETA, w0, tanha(y0_));                                   \
    w1 = fmaf(BETA, w1, tanha(y1_));                                   \
}
// Phase C: full chain
#define STEP(xx) {                                                     \
    u64 y_; IIR(xx, y_);                                               \
    float y0_, y1_; unpack2(y_, y0_, y1_);                             \
    w0 = fmaf(BETA, w0, tanha(y0_));                                   \
    w1 = fmaf(BETA, w1, tanha(y1_));                                   \
    float wp0_ = __shfl_up_sync(0xffffffffu, w0, 1);                   \
    float wp1_ = __shfl_up_sync(0xffffffffu, w1, 1);                   \
    u0 = fmaf(ALPHA, u0, fmaxf(w0 - wp0_, 0.0f));                      \
    u1 = fmaf(ALPHA, u1, fmaxf(w1 - wp1_, 0.0f));                      \
}

    int g = ws >> 2;                     // group index (4 samples/group)
    const int gWWEnd  = wsw >> 2;        // end of z-only phase
    const int gWarmEnd = cstart >> 2;
    const int gEnd = (cstart + CHUNK) >> 2;
    const int gLast = (T >> 2) - 1;

    float4 a = __ldg(xa4 + g);
    float4 b = __ldg(xb4 + g);

    // Phase A: settle poles only (no tanh/shfl/u).
    for (; g < gWWEnd; ) {
        const int gn = g + 1;
        const float4 an = __ldg(xa4 + gn);
        const float4 bn = __ldg(xb4 + gn);
        STEP_Z(pack2(a.x, b.x)); STEP_Z(pack2(a.y, b.y));
        STEP_Z(pack2(a.z, b.z)); STEP_Z(pack2(a.w, b.w));
        a = an; b = bn; g = gn;
    }

    // Phase B: settle beta state w (z keeps settling).
    for (; g < gWarmEnd; ) {
        const int gn = g + 1;
        const float4 an = __ldg(xa4 + gn);
        const float4 bn = __ldg(xb4 + gn);
        STEP_ZW(pack2(a.x, b.x)); STEP_ZW(pack2(a.y, b.y));
        STEP_ZW(pack2(a.z, b.z)); STEP_ZW(pack2(a.w, b.w));
        a = an; b = bn; g = gn;
    }

    // Phase C: full chain; frames at g % 64 == 0; store 0.5*u (descale).
    for (; g < gEnd; g++) {
        const int gn = (g + 1 > gLast) ? gLast : g + 1;
        const float4 an = __ldg(xa4 + gn);
        const float4 bn = __ldg(xb4 + gn);
        STEP(pack2(a.x, b.x));
        if ((g & 63) == 0) {
            if (doStore) { outA[g >> 6] = 0.5f * u0; outB[g >> 6] = 0.5f * u1; }
        }
        STEP(pack2(a.y, b.y));
        STEP(pack2(a.z, b.z));
        STEP(pack2(a.w, b.w));
        a = an; b = bn;
    }
#undef STEP
#undef STEP_ZW
#undef STEP_Z
#undef IIR

    // Chunk tail sum (descaled) for the cross-chunk correction.
    if (doStore) {
        g_S[(c * BS + 2 * p)     * NCH + ch] = 0.5f * u0;
        g_S[(c * BS + 2 * p + 1) * NCH + ch] = 0.5f * u1;
    }
}

// Fully parallel truncated correction:
//   U(c) = S[c-1] + q*S[c-2] + q^2*S[c-3]  (tail <= e^-12, below error floor)
__global__ void fixup_kernel(float* __restrict__ out)
{
    int tid = blockIdx.x * blockDim.x + threadIdx.x;   // over NCHUNK*BS*NCH
    if (tid >= NCHUNK * BS * NCH) return;
    const int ch = tid % NCH;
    const int b  = (tid / NCH) % BS;
    const int c  = tid / (BS * NCH);
    if (c == 0) return;                 // U(0) = 0

    const int base = b * NCH + ch;
    float U = g_S[(c - 1) * (BS * NCH) + base];
    if (c >= 2) U = fmaf(Q1, g_S[(c - 2) * (BS * NCH) + base], U);
    if (c >= 3) U = fmaf(Q2, g_S[(c - 3) * (BS * NCH) + base], U);

    float* o = out + base * NFRM;
    o[2 * c]     += A_POW_1   * U;
    o[2 * c + 1] += A_POW_257 * U;
}

extern "C" void kernel_launch(void* const* d_in, const int* in_sizes, int n_in,
                              void* d_out, int out_size)
{
    const float* wav = (const float*)d_in[0];   // (BS, T)
    const float* cB  = (const float*)d_in[1];   // (NCH, 5)
    const float* cA  = (const float*)d_in[2];   // (NCH, 5)
    float* out = (float*)d_out;                 // (BS, NCH, NFRM)

    const int nWarps = 5 * (BS / 2) * NCHUNK;   // 2500
    aud_spec_kernel<<<nWarps / 4, 128>>>(wav, cB, cA, out);

    const int nFix = NCHUNK * BS * NCH;
    fixup_kernel<<<(nFix + 255) / 256, 256>>>(out);
}

// round 8
// speedup vs baseline: 2.0150x; 1.0273x over previous
#include <cuda_runtime.h>

#define NCH    129
#define T      64000
#define BS     8
#define NFRM   250
#define NCHUNK 125
#define CHUNK  512       // 2 frames per chunk
#define WARM   384       // z warm total; 0.97^384 = e^-11.7
#define WARMW  128       // w warm (beta^128 = e^-16)

#define ALPHA  0.992217938260243520f   // exp(-1/128)
#define BETA   0.882496902584595400f   // exp(-1/8)

// alpha powers for the truncated cross-chunk correction
#define Q1     0.0183156388887342f     // alpha^512  = e^-4
#define Q2     0.0003354626279025f     // alpha^1024 = e^-8
#define A_POW_1     0.9922179382602435f   // alpha^1
#define A_POW_257   0.1342820882f         // alpha^257

typedef unsigned long long u64;

// Per-chunk local-alpha-IIR tail sums: S[c][b][ch]
__device__ float g_S[NCHUNK * BS * NCH];

__device__ __forceinline__ u64 pack2(float lo, float hi) {
    u64 r; asm("mov.b64 %0, {%1, %2};" : "=l"(r) : "f"(lo), "f"(hi)); return r;
}
__device__ __forceinline__ void unpack2(u64 v, float& lo, float& hi) {
    asm("mov.b64 {%0, %1}, %2;" : "=f"(lo), "=f"(hi) : "l"(v));
}
#define FMA2(d,a,b,c) asm("fma.rn.f32x2 %0, %1, %2, %3;" : "=l"(d) : "l"(a), "l"(b), "l"(c))
#define MUL2(d,a,b)   asm("mul.rn.f32x2 %0, %1, %2;"     : "=l"(d) : "l"(a), "l"(b))
__device__ __forceinline__ float tanha(float x) {
    float r; asm("tanh.approx.f32 %0, %1;" : "=f"(r) : "f"(x)); return r;
}

__global__ __launch_bounds__(128)
void aud_spec_kernel(const float* __restrict__ wav,
                     const float* __restrict__ cB,
                     const float* __restrict__ cA,
                     float* __restrict__ out)
{
    // One warp per (channel-group w, batch-pair p, time-chunk c).
    const int warpId = blockIdx.x * 4 + (threadIdx.x >> 5);
    const int w    = warpId % 5;
    const int rem  = warpId / 5;
    const int p    = rem % (BS / 2);
    const int c    = rem / (BS / 2);
    const int lane = threadIdx.x & 31;

    const int chRaw = 31 * w + lane;
    const int ch    = (chRaw > NCH - 1) ? (NCH - 1) : chRaw;

    const float* Bc = cB + ch * 5;
    const float* Ac = cA + ch * 5;
    // Fold the sigmoid's 1/2 argument scale into B (tanh form).
    const float b0 = 0.5f * Bc[0], b1 = 0.5f * Bc[1], b2 = 0.5f * Bc[2],
                b3 = 0.5f * Bc[3], b4 = 0.5f * Bc[4];
    const u64 B0p = pack2(b0, b0), B1p = pack2(b1, b1), B2p = pack2(b2, b2),
              B3p = pack2(b3, b3), B4p = pack2(b4, b4);
    const u64 A1p = pack2(-Ac[1], -Ac[1]);
    const u64 A2p = pack2(-Ac[2], -Ac[2]);
    const u64 A3p = pack2(-Ac[3], -Ac[3]);
    const u64 A4p = pack2(-Ac[4], -Ac[4]);

    u64 z0 = 0, z1 = 0, z2 = 0, z3 = 0;   // packed IIR state (TDF-II)
    float w0 = 0.f, w1 = 0.f;              // w = beta*w + tanh(y)
    float u0 = 0.f, u1 = 0.f;              // scaled alpha IIR (local)

    const float4* xa4 = reinterpret_cast<const float4*>(wav + (2 * p)     * T);
    const float4* xb4 = reinterpret_cast<const float4*>(wav + (2 * p + 1) * T);

    const int cstart = c * CHUNK;
    int ws = cstart - WARM;
    if (ws < 0) ws = 0;
    int wsw = cstart - WARMW;
    if (wsw < 0) wsw = 0;

    const bool doStore = (chRaw <= NCH - 1) && (lane > 0 || w == 0);
    float* outA = out + ((2 * p)     * NCH + ch) * NFRM;
    float* outB = out + ((2 * p + 1) * NCH + ch) * NFRM;

// IIR core (shared by all phases)
#define IIR(xx, y_) {                                                  \
    u64 t_;                                                            \
    FMA2(y_, B0p, (xx), z0);                                           \
    FMA2(t_, B1p, (xx), z1); FMA2(z0, A1p, y_, t_);                    \
    FMA2(t_, B2p, (xx), z2); FMA2(z1, A2p, y_, t_);                    \
    FMA2(t_, B3p, (xx), z3); FMA2(z2, A3p, y_, t_);                    \
    MUL2(t_, B4p, (xx));     FMA2(z3, A4p, y_, t_);                    \
}
// Phase A: z only
#define STEP_Z(xx) { u64 y_; IIR(xx, y_); (void)y_; }
// Phase B: z + w
#define STEP_ZW(xx) {                                                  \
    u64 y_; IIR(xx, y_);                                               \
    float y0_, y1_; unpack2(y_, y0_, y1_);                             \
    w0 = fmaf(BETA, w0, tanha(y0_));                                   \
    w1 = fmaf(BETA, w1, tanha(y1_));                                   \
}
// Phase C, software-pipelined shfl: consume LAST step's pending shfl
// (wq,pw), then issue this step's shfl. u lags by one step.
#define STEP_P(xx) {                                                   \
    u64 y_; IIR(xx, y_);                                               \
    float y0_, y1_; unpack2(y_, y0_, y1_);                             \
    w0 = fmaf(BETA, w0, tanha(y0_));                                   \
    w1 = fmaf(BETA, w1, tanha(y1_));                                   \
    u0 = fmaf(ALPHA, u0, fmaxf(wq0 - pw0, 0.0f));                      \
    u1 = fmaf(ALPHA, u1, fmaxf(wq1 - pw1, 0.0f));                      \
    pw0 = __shfl_up_sync(0xffffffffu, w0, 1);                          \
    pw1 = __shfl_up_sync(0xffffffffu, w1, 1);                          \
    wq0 = w0; wq1 = w1;                                                \
}

    int g = ws >> 2;                     // group index (4 samples/group)
    const int gWWEnd  = wsw >> 2;        // end of z-only phase
    const int gWarmEnd = cstart >> 2;
    const int gEnd = (cstart + CHUNK) >> 2;
    const int gLast = (T >> 2) - 1;

    float4 a = __ldg(xa4 + g);
    float4 b = __ldg(xb4 + g);

    // Phase A: settle poles only.
    for (; g < gWWEnd; ) {
        const int gn = g + 1;
        const float4 an = __ldg(xa4 + gn);
        const float4 bn = __ldg(xb4 + gn);
        STEP_Z(pack2(a.x, b.x)); STEP_Z(pack2(a.y, b.y));
        STEP_Z(pack2(a.z, b.z)); STEP_Z(pack2(a.w, b.w));
        a = an; b = bn; g = gn;
    }

    // Phase B: settle beta state w.
    for (; g < gWarmEnd; ) {
        const int gn = g + 1;
        const float4 an = __ldg(xa4 + gn);
        const float4 bn = __ldg(xb4 + gn);
        STEP_ZW(pack2(a.x, b.x)); STEP_ZW(pack2(a.y, b.y));
        STEP_ZW(pack2(a.z, b.z)); STEP_ZW(pack2(a.w, b.w));
        a = an; b = bn; g = gn;
    }
    u0 = 0.f; u1 = 0.f;                  // zero-init local alpha IIR
    // Prime the shfl pipeline: first consume is a no-op (d = wq - pw = 0).
    float wq0 = w0, wq1 = w1;
    float pw0 = w0, pw1 = w1;

    // Phase C: frames at g % 64 == 0; u lags one step, flushed at stores.
    for (; g < gEnd; g++) {
        const int gn = (g + 1 > gLast) ? gLast : g + 1;
        const float4 an = __ldg(xa4 + gn);
        const float4 bn = __ldg(xb4 + gn);
        STEP_P(pack2(a.x, b.x));
        if ((g & 63) == 0) {
            // Flush pending diff (d at frame time), store, neutralize pending.
            u0 = fmaf(ALPHA, u0, fmaxf(wq0 - pw0, 0.0f));
            u1 = fmaf(ALPHA, u1, fmaxf(wq1 - pw1, 0.0f));
            if (doStore) { outA[g >> 6] = 0.5f * u0; outB[g >> 6] = 0.5f * u1; }
            pw0 = wq0; pw1 = wq1;        // next consume becomes a no-op
        }
        STEP_P(pack2(a.y, b.y));
        STEP_P(pack2(a.z, b.z));
        STEP_P(pack2(a.w, b.w));
        a = an; b = bn;
    }

    // Final flush: include the last step's pending diff, then emit S_c.
    u0 = fmaf(ALPHA, u0, fmaxf(wq0 - pw0, 0.0f));
    u1 = fmaf(ALPHA, u1, fmaxf(wq1 - pw1, 0.0f));
#undef STEP_P
#undef STEP_ZW
#undef STEP_Z
#undef IIR

    if (doStore) {
        g_S[(c * BS + 2 * p)     * NCH + ch] = 0.5f * u0;
        g_S[(c * BS + 2 * p + 1) * NCH + ch] = 0.5f * u1;
    }
}

// Fully parallel truncated correction:
//   U(c) = S[c-1] + q*S[c-2] + q^2*S[c-3]  (tail <= e^-12, below error floor)
__global__ void fixup_kernel(float* __restrict__ out)
{
    int tid = blockIdx.x * blockDim.x + threadIdx.x;   // over NCHUNK*BS*NCH
    if (tid >= NCHUNK * BS * NCH) return;
    const int ch = tid % NCH;
    const int b  = (tid / NCH) % BS;
    const int c  = tid / (BS * NCH);
    if (c == 0) return;                 // U(0) = 0

    const int base = b * NCH + ch;
    float U = g_S[(c - 1) * (BS * NCH) + base];
    if (c >= 2) U = fmaf(Q1, g_S[(c - 2) * (BS * NCH) + base], U);
    if (c >= 3) U = fmaf(Q2, g_S[(c - 3) * (BS * NCH) + base], U);

    float* o = out + base * NFRM;
    o[2 * c]     += A_POW_1   * U;
    o[2 * c + 1] += A_POW_257 * U;
}

extern "C" void kernel_launch(void* const* d_in, const int* in_sizes, int n_in,
                              void* d_out, int out_size)
{
    const float* wav = (const float*)d_in[0];   // (BS, T)
    const float* cB  = (const float*)d_in[1];   // (NCH, 5)
    const float* cA  = (const float*)d_in[2];   // (NCH, 5)
    float* out = (float*)d_out;                 // (BS, NCH, NFRM)

    const int nWarps = 5 * (BS / 2) * NCHUNK;   // 2500
    aud_spec_kernel<<<nWarps / 4, 128>>>(wav, cB, cA, out);

    const int nFix = NCHUNK * BS * NCH;
    fixup_kernel<<<(nFix + 255) / 256, 256>>>(out);
}